// round 1
// baseline (speedup 1.0000x reference)
#include <cuda_runtime.h>

#define HW 16384
// ---------------- scratch (device globals; no allocations) ----------------
__device__ float g_t  [8ULL * 384 * HW];   // pos-conv output t
__device__ float g_qkv[8ULL * 384 * HW];   // grouped-conv qkv
__device__ float g_y2 [8ULL * 128 * HW];   // d3|d5 conv outputs on x
__device__ float g_G  [8 * 8 * 16 * 16];   // raw Gram q_raw . k_raw^T per (b,h)
__device__ float g_ssq[2 * 8 * 8 * 16];    // [0:1024) ssq_q, [1024:2048) ssq_k
__device__ float g_A  [8 * 8 * 16 * 16];   // softmax attention
__device__ float g_M  [8 * 128 * 128];     // per-batch proj[:, :128] @ A_blockdiag

// ---------------- zero accumulators (must rerun every replay) ----------------
__global__ void zero_kernel() {
    int i = blockIdx.x * 256 + threadIdx.x;
    if (i < 16384) g_G[i] = 0.f;
    if (i < 2048)  g_ssq[i] = 0.f;
}

// ---------------- Kernel A: t[b,oc,n] = pos_b[oc] + sum_ic pos_w[oc,ic] x[b,ic,n]
// Tile: 64 oc x 256 n, K=128 in chunks of 16. 256 threads, 8x8 per thread.
__global__ void __launch_bounds__(256) pos_conv_kernel(
    const float* __restrict__ x, const float* __restrict__ w, const float* __restrict__ bias) {
    __shared__ float Xs[16][256];
    __shared__ float Ws[64][17];
    const int b = blockIdx.z, oc0 = blockIdx.y * 64, n0 = blockIdx.x * 256;
    const int tid = threadIdx.x;
    const int tx = tid & 31, ty = tid >> 5;
    const int nl = tx * 4;          // thread owns n: nl..nl+3 and nl+128..nl+131
    const int ol = ty * 8;          // thread owns oc: ol..ol+7
    float acc[8][8];
    #pragma unroll
    for (int i = 0; i < 8; i++) {
        float bv = bias[oc0 + ol + i];
        #pragma unroll
        for (int j = 0; j < 8; j++) acc[i][j] = bv;
    }
    const float* xb = x + (size_t)b * 128 * HW + n0;
    for (int kk = 0; kk < 128; kk += 16) {
        #pragma unroll
        for (int l = tid; l < 16 * 64; l += 256) {           // float4 units
            int r = l >> 6, c4 = l & 63;
            *(float4*)&Xs[r][c4 * 4] = *(const float4*)(xb + (size_t)(kk + r) * HW + c4 * 4);
        }
        #pragma unroll
        for (int l = tid; l < 1024; l += 256) {
            int r = l >> 4, cc = l & 15;
            Ws[r][cc] = w[(oc0 + r) * 128 + kk + cc];
        }
        __syncthreads();
        #pragma unroll
        for (int k = 0; k < 16; k++) {
            float4 b0 = *(float4*)&Xs[k][nl];
            float4 b1 = *(float4*)&Xs[k][nl + 128];
            #pragma unroll
            for (int i = 0; i < 8; i++) {
                float a = Ws[ol + i][k];
                acc[i][0] += a * b0.x; acc[i][1] += a * b0.y;
                acc[i][2] += a * b0.z; acc[i][3] += a * b0.w;
                acc[i][4] += a * b1.x; acc[i][5] += a * b1.y;
                acc[i][6] += a * b1.z; acc[i][7] += a * b1.w;
            }
        }
        __syncthreads();
    }
    float* tb = g_t + ((size_t)b * 384 + oc0) * HW + n0;
    #pragma unroll
    for (int i = 0; i < 8; i++) {
        *(float4*)&tb[(size_t)(ol + i) * HW + nl]       = make_float4(acc[i][0], acc[i][1], acc[i][2], acc[i][3]);
        *(float4*)&tb[(size_t)(ol + i) * HW + nl + 128] = make_float4(acc[i][4], acc[i][5], acc[i][6], acc[i][7]);
    }
}

// ---------------- grouped convs (2 in-ch per group; c<SPLIT: 3x3 pad1, else 5x5 pad2)
// 32x32 spatial tile per block, 256 threads, each thread 4 consecutive rows.
template <int NCOUT, int SPLIT, bool IN_IS_T>
__global__ void __launch_bounds__(256) grouped_conv_kernel(
    const float* __restrict__ xin,
    const float* __restrict__ w3, const float* __restrict__ b3,
    const float* __restrict__ w5, const float* __restrict__ b5) {
    __shared__ float S[2][36][36];
    __shared__ float Wsm[50];
    const int tid = threadIdx.x;
    const int tx = tid & 31, ty = tid >> 5;
    const int c = blockIdx.y, b = blockIdx.z;
    const int tx0 = (blockIdx.x & 3) * 32, ty0 = (blockIdx.x >> 2) * 32;
    const bool is3 = (c < SPLIT);
    const int INC = IN_IS_T ? 384 : 128;
    const float* inbase = IN_IS_T ? g_t : xin;
    const float* inb = inbase + ((size_t)b * INC + (is3 ? 2 * c : 2 * (c - SPLIT))) * HW;
    if (is3) { if (tid < 18) Wsm[tid] = w3[c * 18 + tid]; }
    else     { if (tid < 50) Wsm[tid] = w5[(c - SPLIT) * 50 + tid]; }
    for (int l = tid; l < 2 * 36 * 36; l += 256) {
        int cc = l / 1296; int rem = l - cc * 1296;
        int sy = rem / 36, sx = rem - sy * 36;
        int gy = ty0 - 2 + sy, gx = tx0 - 2 + sx;
        float v = 0.f;
        if ((unsigned)gy < 128u && (unsigned)gx < 128u)
            v = inb[(size_t)cc * HW + gy * 128 + gx];
        S[cc][sy][sx] = v;
    }
    __syncthreads();
    float bv = is3 ? b3[c] : b5[c - SPLIT];
    float acc[4] = {bv, bv, bv, bv};
    const int oy0 = ty * 4;
    if (is3) {
        #pragma unroll
        for (int cc = 0; cc < 2; cc++)
            #pragma unroll
            for (int ky = 0; ky < 3; ky++)
                #pragma unroll
                for (int kx = 0; kx < 3; kx++) {
                    float wv = Wsm[cc * 9 + ky * 3 + kx];
                    #pragma unroll
                    for (int j = 0; j < 4; j++)
                        acc[j] += wv * S[cc][oy0 + j + 1 + ky][tx + 1 + kx];
                }
    } else {
        #pragma unroll
        for (int cc = 0; cc < 2; cc++)
            #pragma unroll
            for (int ky = 0; ky < 5; ky++)
                #pragma unroll
                for (int kx = 0; kx < 5; kx++) {
                    float wv = Wsm[cc * 25 + ky * 5 + kx];
                    #pragma unroll
                    for (int j = 0; j < 4; j++)
                        acc[j] += wv * S[cc][oy0 + j + ky][tx + kx];
                }
    }
    float* ob = (IN_IS_T ? g_qkv : g_y2) + ((size_t)b * NCOUT + c) * HW;
    #pragma unroll
    for (int j = 0; j < 4; j++)
        ob[(ty0 + oy0 + j) * 128 + tx0 + tx] = acc[j];
}

// ---------------- Kernel C: per (b,h) Gram G[d,e] = sum_n q[d,n] k[e,n], plus row sumsq
// grid (64 bh, 16 n-chunks of 1024). 256 threads: 16 (d4,e4)-quads x 16 n-strides.
__global__ void __launch_bounds__(256) qk_reduce_kernel() {
    __shared__ float Qs[16][257];
    __shared__ float Ks[16][257];
    const int tid = threadIdx.x;
    const int bh = blockIdx.x;
    const int b = bh >> 3, h = bh & 7;
    const int quad = tid & 15, ng = tid >> 4;
    const int d4 = (quad >> 2) * 4, e4 = (quad & 3) * 4;
    const float* q0 = g_qkv + ((size_t)b * 384 + h * 16) * HW;
    const float* k0 = g_qkv + ((size_t)b * 384 + 128 + h * 16) * HW;
    const int nbase = blockIdx.y * 1024;
    float acc[4][4] = {};
    float sq[4] = {0, 0, 0, 0}, sk[4] = {0, 0, 0, 0};
    for (int sub = 0; sub < 4; sub++) {
        int nb = nbase + sub * 256;
        for (int l = tid; l < 4096; l += 256) {
            int r = l >> 8, cc = l & 255;
            Qs[r][cc] = q0[(size_t)r * HW + nb + cc];
            Ks[r][cc] = k0[(size_t)r * HW + nb + cc];
        }
        __syncthreads();
        #pragma unroll
        for (int i = 0; i < 16; i++) {
            int n = ng + 16 * i;
            float qv[4], kv[4];
            #pragma unroll
            for (int j = 0; j < 4; j++) { qv[j] = Qs[d4 + j][n]; kv[j] = Ks[e4 + j][n]; }
            #pragma unroll
            for (int j = 0; j < 4; j++)
                #pragma unroll
                for (int m = 0; m < 4; m++) acc[j][m] += qv[j] * kv[m];
            if (e4 == 0) {
                #pragma unroll
                for (int j = 0; j < 4; j++) sq[j] += qv[j] * qv[j];
            }
            if (d4 == 0) {
                #pragma unroll
                for (int j = 0; j < 4; j++) sk[j] += kv[j] * kv[j];
            }
        }
        __syncthreads();
    }
    float* Gb = g_G + bh * 256;
    #pragma unroll
    for (int j = 0; j < 4; j++)
        #pragma unroll
        for (int m = 0; m < 4; m++)
            atomicAdd(&Gb[(d4 + j) * 16 + e4 + m], acc[j][m]);
    if (e4 == 0) {
        #pragma unroll
        for (int j = 0; j < 4; j++) atomicAdd(&g_ssq[bh * 16 + d4 + j], sq[j]);
    }
    if (d4 == 0) {
        #pragma unroll
        for (int j = 0; j < 4; j++) atomicAdd(&g_ssq[1024 + bh * 16 + e4 + j], sk[j]);
    }
}

// ---------------- Kernel D1: A = softmax_e( G / (||q_d|| ||k_e||) * temp[h] )
__global__ void attn_kernel(const float* __restrict__ temp) {
    __shared__ float L[16][17];
    __shared__ float E[16][17];
    int bh = blockIdx.x, h = bh & 7;
    int tid = threadIdx.x;
    int d = tid >> 4, e = tid & 15;
    float nq = fmaxf(sqrtf(g_ssq[bh * 16 + d]), 1e-12f);
    float nk = fmaxf(sqrtf(g_ssq[1024 + bh * 16 + e]), 1e-12f);
    float logit = g_G[bh * 256 + tid] / (nq * nk) * temp[h];
    L[d][e] = logit;
    __syncthreads();
    float m = -1e30f;
    #pragma unroll
    for (int i = 0; i < 16; i++) m = fmaxf(m, L[d][i]);
    float ex = expf(logit - m);
    E[d][e] = ex;
    __syncthreads();
    float s = 0.f;
    #pragma unroll
    for (int i = 0; i < 16; i++) s += E[d][i];
    g_A[bh * 256 + tid] = ex / s;
}

// ---------------- Kernel D2: M[b,oc,h*16+e] = sum_d proj[oc, h*16+d] * A[b,h,d,e]
__global__ void mfold_kernel(const float* __restrict__ proj) {
    int oc = blockIdx.x, b = blockIdx.y;
    int hc = threadIdx.x;  // 0..127
    int h = hc >> 4, e = hc & 15;
    float s = 0.f;
    #pragma unroll
    for (int d = 0; d < 16; d++)
        s += proj[oc * 256 + h * 16 + d] * g_A[((b * 8 + h) * 16 + d) * 16 + e];
    g_M[((size_t)b * 128 + oc) * 128 + hc] = s;
}

// ---------------- Kernel E2: out[b,oc,n] = sum_{c<128} M[b,oc,c] v[c,n] + sum_{c<128} proj[oc,128+c] y2[c,n]
__global__ void __launch_bounds__(256) final_kernel(const float* __restrict__ proj, float* __restrict__ out) {
    __shared__ float Xs[16][256];
    __shared__ float Ws[64][17];
    const int b = blockIdx.z, oc0 = blockIdx.y * 64, n0 = blockIdx.x * 256;
    const int tid = threadIdx.x;
    const int tx = tid & 31, ty = tid >> 5;
    const int nl = tx * 4, ol = ty * 8;
    float acc[8][8] = {};
    for (int kk = 0; kk < 256; kk += 16) {
        const float* src = (kk < 128)
            ? g_qkv + ((size_t)b * 384 + 256 + kk) * HW + n0
            : g_y2 + ((size_t)b * 128 + (kk - 128)) * HW + n0;
        #pragma unroll
        for (int l = tid; l < 16 * 64; l += 256) {
            int r = l >> 6, c4 = l & 63;
            *(float4*)&Xs[r][c4 * 4] = *(const float4*)(src + (size_t)r * HW + c4 * 4);
        }
        #pragma unroll
        for (int l = tid; l < 1024; l += 256) {
            int r = l >> 4, cc = l & 15;
            int k = kk + cc;
            Ws[r][cc] = (kk < 128) ? g_M[((size_t)b * 128 + oc0 + r) * 128 + k]
                                   : proj[(oc0 + r) * 256 + k];
        }
        __syncthreads();
        #pragma unroll
        for (int k = 0; k < 16; k++) {
            float4 b0 = *(float4*)&Xs[k][nl];
            float4 b1 = *(float4*)&Xs[k][nl + 128];
            #pragma unroll
            for (int i = 0; i < 8; i++) {
                float a = Ws[ol + i][k];
                acc[i][0] += a * b0.x; acc[i][1] += a * b0.y;
                acc[i][2] += a * b0.z; acc[i][3] += a * b0.w;
                acc[i][4] += a * b1.x; acc[i][5] += a * b1.y;
                acc[i][6] += a * b1.z; acc[i][7] += a * b1.w;
            }
        }
        __syncthreads();
    }
    float* ob = out + ((size_t)b * 128 + oc0) * HW + n0;
    #pragma unroll
    for (int i = 0; i < 8; i++) {
        *(float4*)&ob[(size_t)(ol + i) * HW + nl]       = make_float4(acc[i][0], acc[i][1], acc[i][2], acc[i][3]);
        *(float4*)&ob[(size_t)(ol + i) * HW + nl + 128] = make_float4(acc[i][4], acc[i][5], acc[i][6], acc[i][7]);
    }
}

// ---------------- launch ----------------
extern "C" void kernel_launch(void* const* d_in, const int* in_sizes, int n_in,
                              void* d_out, int out_size) {
    const float* x      = (const float*)d_in[0];
    const float* pos_w  = (const float*)d_in[1];
    const float* pos_b  = (const float*)d_in[2];
    const float* qd3_w  = (const float*)d_in[3];
    const float* qd3_b  = (const float*)d_in[4];
    const float* qd5_w  = (const float*)d_in[5];
    const float* qd5_b  = (const float*)d_in[6];
    const float* temp   = (const float*)d_in[7];
    const float* d3_w   = (const float*)d_in[8];
    const float* d3_b   = (const float*)d_in[9];
    const float* d5_w   = (const float*)d_in[10];
    const float* d5_b   = (const float*)d_in[11];
    const float* proj_w = (const float*)d_in[12];
    float* out = (float*)d_out;

    zero_kernel<<<64, 256>>>();
    pos_conv_kernel<<<dim3(64, 6, 8), 256>>>(x, pos_w, pos_b);
    grouped_conv_kernel<384, 192, true ><<<dim3(16, 384, 8), 256>>>(nullptr, qd3_w, qd3_b, qd5_w, qd5_b);
    grouped_conv_kernel<128,  64, false><<<dim3(16, 128, 8), 256>>>(x, d3_w, d3_b, d5_w, d5_b);
    qk_reduce_kernel<<<dim3(64, 16), 256>>>();
    attn_kernel<<<64, 256>>>(temp);
    mfold_kernel<<<dim3(128, 8), 128>>>(proj_w);
    final_kernel<<<dim3(64, 2, 8), 256>>>(proj_w, out);
}

// round 2
// speedup vs baseline: 1.0548x; 1.0548x over previous
#include <cuda_runtime.h>

#define HW 16384
// ---------------- scratch (device globals; no allocations) ----------------
__device__ float g_t  [8ULL * 384 * HW];   // pos-conv output t
__device__ float g_qkv[8ULL * 384 * HW];   // grouped-conv qkv
__device__ float g_y2 [8ULL * 128 * HW];   // d3|d5 conv outputs on x
__device__ float g_G  [8 * 8 * 16 * 16];   // raw Gram q_raw . k_raw^T per (b,h)
__device__ float g_ssq[2 * 8 * 8 * 16];    // [0:1024) ssq_q, [1024:2048) ssq_k
__device__ float g_A  [8 * 8 * 16 * 16];   // softmax attention
__device__ float g_M  [8 * 128 * 128];     // per-batch proj[:, :128] @ A_blockdiag

// ---------------- zero accumulators (must rerun every replay) ----------------
__global__ void zero_kernel() {
    int i = blockIdx.x * 256 + threadIdx.x;
    if (i < 16384) g_G[i] = 0.f;
    if (i < 2048)  g_ssq[i] = 0.f;
}

// ---------------- Kernel A: t[b,oc,n] = pos_b[oc] + sum_ic pos_w[oc,ic] x[b,ic,n]
// Tile: 64 oc x 256 n, K=128 in chunks of 16. 256 threads, 8x8 per thread.
__global__ void __launch_bounds__(256) pos_conv_kernel(
    const float* __restrict__ x, const float* __restrict__ w, const float* __restrict__ bias) {
    __shared__ float Xs[16][256];
    __shared__ float Ws[16][68];           // k-major, 16B-aligned rows
    const int b = blockIdx.z, oc0 = blockIdx.y * 64, n0 = blockIdx.x * 256;
    const int tid = threadIdx.x;
    const int tx = tid & 31, ty = tid >> 5;
    const int nl = tx * 4;          // thread owns n: nl..nl+3 and nl+128..nl+131
    const int ol = ty * 8;          // thread owns oc: ol..ol+7
    float acc[8][8];
    #pragma unroll
    for (int i = 0; i < 8; i++) {
        float bv = bias[oc0 + ol + i];
        #pragma unroll
        for (int j = 0; j < 8; j++) acc[i][j] = bv;
    }
    const float* xb = x + (size_t)b * 128 * HW + n0;
    for (int kk = 0; kk < 128; kk += 16) {
        #pragma unroll
        for (int l = tid; l < 16 * 64; l += 256) {           // float4 units
            int r = l >> 6, c4 = l & 63;
            *(float4*)&Xs[r][c4 * 4] = *(const float4*)(xb + (size_t)(kk + r) * HW + c4 * 4);
        }
        #pragma unroll
        for (int l = tid; l < 1024; l += 256) {
            int oc = l >> 4, kc = l & 15;
            Ws[kc][oc] = w[(oc0 + oc) * 128 + kk + kc];
        }
        __syncthreads();
        #pragma unroll
        for (int k = 0; k < 16; k++) {
            float4 x0 = *(float4*)&Xs[k][nl];
            float4 x1 = *(float4*)&Xs[k][nl + 128];
            float4 wA = *(float4*)&Ws[k][ol];
            float4 wB = *(float4*)&Ws[k][ol + 4];
            float wr[8] = {wA.x, wA.y, wA.z, wA.w, wB.x, wB.y, wB.z, wB.w};
            float xr[8] = {x0.x, x0.y, x0.z, x0.w, x1.x, x1.y, x1.z, x1.w};
            #pragma unroll
            for (int i = 0; i < 8; i++)
                #pragma unroll
                for (int j = 0; j < 8; j++) acc[i][j] += wr[i] * xr[j];
        }
        __syncthreads();
    }
    float* tb = g_t + ((size_t)b * 384 + oc0) * HW + n0;
    #pragma unroll
    for (int i = 0; i < 8; i++) {
        *(float4*)&tb[(size_t)(ol + i) * HW + nl]       = make_float4(acc[i][0], acc[i][1], acc[i][2], acc[i][3]);
        *(float4*)&tb[(size_t)(ol + i) * HW + nl + 128] = make_float4(acc[i][4], acc[i][5], acc[i][6], acc[i][7]);
    }
}

// ---------------- fused grouped conv: one block = one input-channel pair, computes
// BOTH the 3x3 (pad1) and 5x5 (pad2) outputs. 32x32 spatial tile, 256 threads,
// thread computes 4 consecutive rows for both outputs with register column reuse.
template <bool IN_IS_T>
__global__ void __launch_bounds__(256) fused_gconv_kernel(
    const float* __restrict__ xin,
    const float* __restrict__ w3, const float* __restrict__ b3,
    const float* __restrict__ w5, const float* __restrict__ b5) {
    const int NP = IN_IS_T ? 192 : 64;         // number of channel pairs
    __shared__ float S[2][36][37];
    __shared__ float W3s[18];
    __shared__ float W5s[50];
    const int tid = threadIdx.x;
    const int g = blockIdx.y, b = blockIdx.z;
    const int tx0 = (blockIdx.x & 3) * 32, ty0 = (blockIdx.x >> 2) * 32;
    const int INC = IN_IS_T ? 384 : 128;
    const float* inb = (IN_IS_T ? g_t : xin) + ((size_t)b * INC + 2 * g) * HW;

    if (tid < 18) W3s[tid] = w3[g * 18 + tid];
    if (tid >= 32 && tid < 82) W5s[tid - 32] = w5[g * 50 + (tid - 32)];

    // halo load: warp w handles rows w, w+8, ..., lanes cover 36 cols (l and 32+l)
    {
        const int w = tid >> 5, l = tid & 31;
        const int gx1 = tx0 - 2 + l;
        const int gx2 = tx0 + 30 + l;
        const bool okX1 = (unsigned)gx1 < 128u;
        const bool okX2 = (unsigned)gx2 < 128u;
        #pragma unroll
        for (int cc = 0; cc < 2; cc++) {
            const float* p = inb + (size_t)cc * HW;
            #pragma unroll
            for (int r = w; r < 36; r += 8) {
                int gy = ty0 - 2 + r;
                bool okY = (unsigned)gy < 128u;
                S[cc][r][l] = (okY && okX1) ? p[gy * 128 + gx1] : 0.f;
                if (l < 4)
                    S[cc][r][32 + l] = (okY && okX2) ? p[gy * 128 + gx2] : 0.f;
            }
        }
    }
    __syncthreads();

    const int tx = tid & 31, oy0 = (tid >> 5) * 4;
    float bv3 = b3[g], bv5 = b5[g];
    float a3[4] = {bv3, bv3, bv3, bv3};
    float a5[4] = {bv5, bv5, bv5, bv5};
    #pragma unroll
    for (int cc = 0; cc < 2; cc++) {
        #pragma unroll
        for (int kx = 0; kx < 5; kx++) {
            float v[8];
            #pragma unroll
            for (int r = 0; r < 8; r++) v[r] = S[cc][oy0 + r][tx + kx];
            #pragma unroll
            for (int ky = 0; ky < 5; ky++) {
                float wv = W5s[cc * 25 + ky * 5 + kx];
                #pragma unroll
                for (int j = 0; j < 4; j++) a5[j] += wv * v[j + ky];
            }
            if (kx >= 1 && kx <= 3) {
                #pragma unroll
                for (int ky = 0; ky < 3; ky++) {
                    float wv = W3s[cc * 9 + ky * 3 + (kx - 1)];
                    #pragma unroll
                    for (int j = 0; j < 4; j++) a3[j] += wv * v[j + 1 + ky];
                }
            }
        }
    }
    float* obase = IN_IS_T ? g_qkv : g_y2;
    float* o3 = obase + ((size_t)b * (2 * NP) + g) * HW;
    float* o5 = obase + ((size_t)b * (2 * NP) + NP + g) * HW;
    #pragma unroll
    for (int j = 0; j < 4; j++) {
        int off = (ty0 + oy0 + j) * 128 + tx0 + tx;
        o3[off] = a3[j];
        o5[off] = a5[j];
    }
}

// ---------------- Kernel C: per (b,h) Gram G[d,e] = sum_n q[d,n] k[e,n], plus row sumsq
// grid (64 bh, 16 n-chunks of 1024). 256 threads: 16 (d4,e4)-quads x 16 n-strides.
__global__ void __launch_bounds__(256) qk_reduce_kernel() {
    __shared__ float Qs[16][257];
    __shared__ float Ks[16][257];
    const int tid = threadIdx.x;
    const int bh = blockIdx.x;
    const int b = bh >> 3, h = bh & 7;
    const int quad = tid & 15, ng = tid >> 4;
    const int d4 = (quad >> 2) * 4, e4 = (quad & 3) * 4;
    const float* q0 = g_qkv + ((size_t)b * 384 + h * 16) * HW;
    const float* k0 = g_qkv + ((size_t)b * 384 + 128 + h * 16) * HW;
    const int nbase = blockIdx.y * 1024;
    float acc[4][4] = {};
    float sq[4] = {0, 0, 0, 0}, sk[4] = {0, 0, 0, 0};
    for (int sub = 0; sub < 4; sub++) {
        int nb = nbase + sub * 256;
        for (int l = tid; l < 4096; l += 256) {
            int r = l >> 8, cc = l & 255;
            Qs[r][cc] = q0[(size_t)r * HW + nb + cc];
            Ks[r][cc] = k0[(size_t)r * HW + nb + cc];
        }
        __syncthreads();
        #pragma unroll
        for (int i = 0; i < 16; i++) {
            int n = ng + 16 * i;
            float qv[4], kv[4];
            #pragma unroll
            for (int j = 0; j < 4; j++) { qv[j] = Qs[d4 + j][n]; kv[j] = Ks[e4 + j][n]; }
            #pragma unroll
            for (int j = 0; j < 4; j++)
                #pragma unroll
                for (int m = 0; m < 4; m++) acc[j][m] += qv[j] * kv[m];
            if (e4 == 0) {
                #pragma unroll
                for (int j = 0; j < 4; j++) sq[j] += qv[j] * qv[j];
            }
            if (d4 == 0) {
                #pragma unroll
                for (int j = 0; j < 4; j++) sk[j] += kv[j] * kv[j];
            }
        }
        __syncthreads();
    }
    float* Gb = g_G + bh * 256;
    #pragma unroll
    for (int j = 0; j < 4; j++)
        #pragma unroll
        for (int m = 0; m < 4; m++)
            atomicAdd(&Gb[(d4 + j) * 16 + e4 + m], acc[j][m]);
    if (e4 == 0) {
        #pragma unroll
        for (int j = 0; j < 4; j++) atomicAdd(&g_ssq[bh * 16 + d4 + j], sq[j]);
    }
    if (d4 == 0) {
        #pragma unroll
        for (int j = 0; j < 4; j++) atomicAdd(&g_ssq[1024 + bh * 16 + e4 + j], sk[j]);
    }
}

// ---------------- Kernel D1: A = softmax_e( G / (||q_d|| ||k_e||) * temp[h] )
__global__ void attn_kernel(const float* __restrict__ temp) {
    __shared__ float L[16][17];
    __shared__ float E[16][17];
    int bh = blockIdx.x, h = bh & 7;
    int tid = threadIdx.x;
    int d = tid >> 4, e = tid & 15;
    float nq = fmaxf(sqrtf(g_ssq[bh * 16 + d]), 1e-12f);
    float nk = fmaxf(sqrtf(g_ssq[1024 + bh * 16 + e]), 1e-12f);
    float logit = g_G[bh * 256 + tid] / (nq * nk) * temp[h];
    L[d][e] = logit;
    __syncthreads();
    float m = -1e30f;
    #pragma unroll
    for (int i = 0; i < 16; i++) m = fmaxf(m, L[d][i]);
    float ex = expf(logit - m);
    E[d][e] = ex;
    __syncthreads();
    float s = 0.f;
    #pragma unroll
    for (int i = 0; i < 16; i++) s += E[d][i];
    g_A[bh * 256 + tid] = ex / s;
}

// ---------------- Kernel D2: M[b,oc,h*16+e] = sum_d proj[oc, h*16+d] * A[b,h,d,e]
__global__ void mfold_kernel(const float* __restrict__ proj) {
    int oc = blockIdx.x, b = blockIdx.y;
    int hc = threadIdx.x;  // 0..127
    int h = hc >> 4, e = hc & 15;
    float s = 0.f;
    #pragma unroll
    for (int d = 0; d < 16; d++)
        s += proj[oc * 256 + h * 16 + d] * g_A[((b * 8 + h) * 16 + d) * 16 + e];
    g_M[((size_t)b * 128 + oc) * 128 + hc] = s;
}

// ---------------- Kernel E2: out[b,oc,n] = sum_{c<128} M[b,oc,c] v[c,n] + sum_{c<128} proj[oc,128+c] y2[c,n]
__global__ void __launch_bounds__(256) final_kernel(const float* __restrict__ proj, float* __restrict__ out) {
    __shared__ float Xs[16][256];
    __shared__ float Ws[16][68];
    const int b = blockIdx.z, oc0 = blockIdx.y * 64, n0 = blockIdx.x * 256;
    const int tid = threadIdx.x;
    const int tx = tid & 31, ty = tid >> 5;
    const int nl = tx * 4, ol = ty * 8;
    float acc[8][8] = {};
    for (int kk = 0; kk < 256; kk += 16) {
        const float* src = (kk < 128)
            ? g_qkv + ((size_t)b * 384 + 256 + kk) * HW + n0
            : g_y2 + ((size_t)b * 128 + (kk - 128)) * HW + n0;
        #pragma unroll
        for (int l = tid; l < 16 * 64; l += 256) {
            int r = l >> 6, c4 = l & 63;
            *(float4*)&Xs[r][c4 * 4] = *(const float4*)(src + (size_t)r * HW + c4 * 4);
        }
        #pragma unroll
        for (int l = tid; l < 1024; l += 256) {
            int oc = l >> 4, kc = l & 15;
            int k = kk + kc;
            Ws[kc][oc] = (kk < 128) ? g_M[((size_t)b * 128 + oc0 + oc) * 128 + k]
                                    : proj[(oc0 + oc) * 256 + k];
        }
        __syncthreads();
        #pragma unroll
        for (int k = 0; k < 16; k++) {
            float4 x0 = *(float4*)&Xs[k][nl];
            float4 x1 = *(float4*)&Xs[k][nl + 128];
            float4 wA = *(float4*)&Ws[k][ol];
            float4 wB = *(float4*)&Ws[k][ol + 4];
            float wr[8] = {wA.x, wA.y, wA.z, wA.w, wB.x, wB.y, wB.z, wB.w};
            float xr[8] = {x0.x, x0.y, x0.z, x0.w, x1.x, x1.y, x1.z, x1.w};
            #pragma unroll
            for (int i = 0; i < 8; i++)
                #pragma unroll
                for (int j = 0; j < 8; j++) acc[i][j] += wr[i] * xr[j];
        }
        __syncthreads();
    }
    float* ob = out + ((size_t)b * 128 + oc0) * HW + n0;
    #pragma unroll
    for (int i = 0; i < 8; i++) {
        *(float4*)&ob[(size_t)(ol + i) * HW + nl]       = make_float4(acc[i][0], acc[i][1], acc[i][2], acc[i][3]);
        *(float4*)&ob[(size_t)(ol + i) * HW + nl + 128] = make_float4(acc[i][4], acc[i][5], acc[i][6], acc[i][7]);
    }
}

// ---------------- launch ----------------
extern "C" void kernel_launch(void* const* d_in, const int* in_sizes, int n_in,
                              void* d_out, int out_size) {
    const float* x      = (const float*)d_in[0];
    const float* pos_w  = (const float*)d_in[1];
    const float* pos_b  = (const float*)d_in[2];
    const float* qd3_w  = (const float*)d_in[3];
    const float* qd3_b  = (const float*)d_in[4];
    const float* qd5_w  = (const float*)d_in[5];
    const float* qd5_b  = (const float*)d_in[6];
    const float* temp   = (const float*)d_in[7];
    const float* d3_w   = (const float*)d_in[8];
    const float* d3_b   = (const float*)d_in[9];
    const float* d5_w   = (const float*)d_in[10];
    const float* d5_b   = (const float*)d_in[11];
    const float* proj_w = (const float*)d_in[12];
    float* out = (float*)d_out;

    zero_kernel<<<64, 256>>>();
    pos_conv_kernel<<<dim3(64, 6, 8), 256>>>(x, pos_w, pos_b);
    fused_gconv_kernel<true ><<<dim3(16, 192, 8), 256>>>(nullptr, qd3_w, qd3_b, qd5_w, qd5_b);
    fused_gconv_kernel<false><<<dim3(16, 64, 8), 256>>>(x, d3_w, d3_b, d5_w, d5_b);
    qk_reduce_kernel<<<dim3(64, 16), 256>>>();
    attn_kernel<<<64, 256>>>(temp);
    mfold_kernel<<<dim3(128, 8), 128>>>(proj_w);
    final_kernel<<<dim3(64, 2, 8), 256>>>(proj_w, out);
}